// round 1
// baseline (speedup 1.0000x reference)
#include <cuda_runtime.h>
#include <cuda_bf16.h>

// Problem constants
#define BATCH 32
#define IN_F  784
#define H1    1024
#define H2    1024
#define NC    10
#define EPSV  0.1f
#define NROWS (BATCH * NC)   // 320 final-layer rows

// ---------------- scratch (device globals; no allocation allowed) ----------
__device__ float g_r1[H1];
__device__ float g_nom1[BATCH * H1];
__device__ float g_d1[BATCH * H1];
__device__ float g_l1m[BATCH * H1];
__device__ float g_E2[BATCH * H2];
__device__ float g_d2[BATCH * H2];
__device__ float g_l2m[BATCH * H2];
__device__ float g_nu2[NROWS * H2];
__device__ float g_term[NROWS];
__device__ float g_nu1f[NROWS * H1];
__device__ float g_Ef[NROWS];
__device__ float g_afdot[NROWS];
__device__ float g_cross1f[NROWS];

// ---------------- helpers ---------------------------------------------------
__device__ __forceinline__ float warp_sum(float v) {
    #pragma unroll
    for (int o = 16; o > 0; o >>= 1) v += __shfl_xor_sync(0xFFFFFFFFu, v, o);
    return v;
}

__device__ __forceinline__ void relu_coeffs(float zl, float zu, float& d, float& lm) {
    if (zl >= 0.f)      { d = 1.f; lm = 0.f; }
    else if (zu <= 0.f) { d = 0.f; lm = 0.f; }
    else                { d = zu / (zu - zl); lm = zl; }
}

// ---------------- K0: r1[j] = eps * sum_k |W1[j,k]| ------------------------
__global__ void k_r1(const float* __restrict__ W1) {
    int gw   = (blockIdx.x * blockDim.x + threadIdx.x) >> 5;
    int lane = threadIdx.x & 31;
    if (gw >= H1) return;
    const float* row = W1 + gw * IN_F;
    float s = 0.f;
    for (int k = lane; k < IN_F; k += 32) s += fabsf(row[k]);
    s = warp_sum(s);
    if (lane == 0) g_r1[gw] = EPSV * s;
}

// ---------------- K1: layer-1 bounds (warp per (b,j)) ----------------------
__global__ void k_layer1(const float* __restrict__ x, const float* __restrict__ W1,
                         const float* __restrict__ b1) {
    int gw   = (blockIdx.x * blockDim.x + threadIdx.x) >> 5;   // 0..BATCH*H1-1
    int lane = threadIdx.x & 31;
    int b = gw >> 10, j = gw & (H1 - 1);
    const float* xr = x  + b * IN_F;
    const float* wr = W1 + j * IN_F;
    float s = 0.f;
    for (int k = lane; k < IN_F; k += 32) s += xr[k] * wr[k];
    s = warp_sum(s);
    if (lane == 0) {
        float nom = s + b1[j];
        float r   = g_r1[j];
        float d, lm;
        relu_coeffs(nom - r, nom + r, d, lm);
        g_nom1[gw] = nom;
        g_d1[gw]   = d;
        g_l1m[gw]  = lm;
    }
}

// ---------------- abs-row-sum GEMM -----------------------------------------
// Computes Eout[row] = eps * sum_n | sum_i A[row,i] * W1[i,n] |  over n<784.
// mode 0: A[row,i] = Asrc[row*H1+i] * dscale[b*H1+i]  (b = blockIdx.y), Eout idx = b*H2+row
// mode 1: A[row,i] = Asrc[row*H1+i],                              Eout idx = row
// Block: 256 threads, BM=64 rows, BN=64 n-chunk (zero-padded past 784), BK=16.
__global__ void k_absgemm(const float* __restrict__ W1, const float* __restrict__ Asrc,
                          const float* __restrict__ dscale, float* __restrict__ Eout,
                          int mode) {
    __shared__ float As[16][64];
    __shared__ float Bs[16][64];
    __shared__ float red[64][16];

    const int tid = threadIdx.x;
    const int ty  = tid >> 4;          // 0..15: owns rows 4*ty..4*ty+3
    const int tx  = tid & 15;          // 0..15: owns cols 4*tx..4*tx+3
    const int b   = blockIdx.y;
    const int jr0 = blockIdx.x * 64;

    // A loader: each thread loads one float4 of the 64x16 A tile
    const int alr = tid >> 2;          // row 0..63
    const int alc = (tid & 3) * 4;     // col 0,4,8,12
    // B loader: each thread loads one float4 of the 16x64 B tile
    const int blr = tid >> 4;          // row 0..15
    const int blc = (tid & 15) * 4;    // col 0..60

    const float* Abase  = Asrc + (size_t)(jr0 + alr) * H1 + alc;
    const float* dsbase = (mode == 0) ? (dscale + b * H1 + alc) : nullptr;

    float rowsum[4] = {0.f, 0.f, 0.f, 0.f};

    for (int n0 = 0; n0 < IN_F; n0 += 64) {
        float c[4][4];
        #pragma unroll
        for (int r = 0; r < 4; r++)
            #pragma unroll
            for (int q = 0; q < 4; q++) c[r][q] = 0.f;

        for (int k0 = 0; k0 < H1; k0 += 16) {
            float4 av = *reinterpret_cast<const float4*>(Abase + k0);
            if (mode == 0) {
                const float* ds = dsbase + k0;
                av.x *= ds[0]; av.y *= ds[1]; av.z *= ds[2]; av.w *= ds[3];
            }
            int n = n0 + blc;
            float4 bv = make_float4(0.f, 0.f, 0.f, 0.f);
            if (n < IN_F)   // IN_F % 4 == 0, so a float4 is all-valid or all-invalid
                bv = *reinterpret_cast<const float4*>(W1 + (size_t)(k0 + blr) * IN_F + n);

            __syncthreads();
            As[alc + 0][alr] = av.x;
            As[alc + 1][alr] = av.y;
            As[alc + 2][alr] = av.z;
            As[alc + 3][alr] = av.w;
            *reinterpret_cast<float4*>(&Bs[blr][blc]) = bv;
            __syncthreads();

            #pragma unroll
            for (int kk = 0; kk < 16; kk++) {
                float4 a = *reinterpret_cast<const float4*>(&As[kk][ty * 4]);
                float4 bq = *reinterpret_cast<const float4*>(&Bs[kk][tx * 4]);
                float ar[4] = {a.x, a.y, a.z, a.w};
                float br[4] = {bq.x, bq.y, bq.z, bq.w};
                #pragma unroll
                for (int r = 0; r < 4; r++)
                    #pragma unroll
                    for (int q = 0; q < 4; q++)
                        c[r][q] = fmaf(ar[r], br[q], c[r][q]);
            }
        }
        #pragma unroll
        for (int r = 0; r < 4; r++)
            #pragma unroll
            for (int q = 0; q < 4; q++) rowsum[r] += fabsf(c[r][q]);
    }

    __syncthreads();
    #pragma unroll
    for (int r = 0; r < 4; r++) red[ty * 4 + r][tx] = rowsum[r];
    __syncthreads();
    if (tid < 64) {
        float s = 0.f;
        #pragma unroll
        for (int t = 0; t < 16; t++) s += red[tid][t];
        int oi = (mode == 0) ? (b * H2 + jr0 + tid) : (jr0 + tid);
        Eout[oi] = EPSV * s;
    }
}

// ---------------- K3: layer-2 bounds (warp per (b,j)) ----------------------
// A2 = sum_i nu*nom1 + b2[j];  crossl = sum relu(-nu)*l1m; crossu = sum relu(nu)*l1m
__global__ void k_layer2(const float* __restrict__ W2, const float* __restrict__ b2) {
    int gw   = (blockIdx.x * blockDim.x + threadIdx.x) >> 5;   // 0..BATCH*H2-1
    int lane = threadIdx.x & 31;
    int b = gw >> 10, j = gw & (H2 - 1);
    const float* w2r  = W2     + (size_t)j * H1;
    const float* d1r  = g_d1   + b * H1;
    const float* nomr = g_nom1 + b * H1;
    const float* lmr  = g_l1m  + b * H1;
    float s1 = 0.f, s2 = 0.f, s3 = 0.f;
    for (int i = lane; i < H1; i += 32) {
        float nu = w2r[i] * d1r[i];
        s1 += nu * nomr[i];
        float lm = lmr[i];
        s2 += fmaxf(-nu, 0.f) * lm;
        s3 += fmaxf( nu, 0.f) * lm;
    }
    s1 = warp_sum(s1); s2 = warp_sum(s2); s3 = warp_sum(s3);
    if (lane == 0) {
        float A = s1 + b2[j];
        float E = g_E2[gw];
        float d, lm;
        relu_coeffs(A - E + s2, A + E - s3, d, lm);
        g_d2[gw]  = d;
        g_l2m[gw] = lm;
    }
}

// ---------------- K4: nu2 + bias/cross terms (block per r=(b,j)) -----------
__global__ void k_nu2(const float* __restrict__ W3, const float* __restrict__ b2,
                      const float* __restrict__ b3, const int* __restrict__ y) {
    __shared__ float sA[256], sB[256];
    int r = blockIdx.x;            // 0..319
    int b = r / NC, j = r % NC;
    int yb = y[b];
    const float* wy  = W3 + (size_t)yb * H2;
    const float* wj  = W3 + (size_t)j  * H2;
    const float* d2r = g_d2  + b * H2;
    const float* lmr = g_l2m + b * H2;
    float sa = 0.f, sb = 0.f;
    for (int t = threadIdx.x; t < H2; t += 256) {
        float nu = (wy[t] - wj[t]) * d2r[t];
        g_nu2[(size_t)r * H2 + t] = nu;
        sa += fmaxf(-nu, 0.f) * lmr[t];
        sb += nu * b2[t];
    }
    sA[threadIdx.x] = sa; sB[threadIdx.x] = sb;
    __syncthreads();
    for (int o = 128; o > 0; o >>= 1) {
        if (threadIdx.x < o) {
            sA[threadIdx.x] += sA[threadIdx.x + o];
            sB[threadIdx.x] += sB[threadIdx.x + o];
        }
        __syncthreads();
    }
    if (threadIdx.x == 0)
        g_term[r] = (b3[yb] - b3[j]) + sB[0] + sA[0];
}

// ---------------- K5: nu1f = (nu2 @ W2) * d1  (block = (i-tile, b)) --------
__global__ void k_nu1f(const float* __restrict__ W2) {
    __shared__ float snu[NC][64];
    int b = blockIdx.y;
    int i = blockIdx.x * 128 + threadIdx.x;     // column of W2
    float acc[NC];
    #pragma unroll
    for (int j = 0; j < NC; j++) acc[j] = 0.f;

    for (int t0 = 0; t0 < H2; t0 += 64) {
        __syncthreads();
        for (int idx = threadIdx.x; idx < NC * 64; idx += 128)
            snu[idx >> 6][idx & 63] = g_nu2[(size_t)(b * NC + (idx >> 6)) * H2 + t0 + (idx & 63)];
        __syncthreads();
        for (int t = 0; t < 64; t++) {
            float w = W2[(size_t)(t0 + t) * H1 + i];
            #pragma unroll
            for (int j = 0; j < NC; j++) acc[j] = fmaf(snu[j][t], w, acc[j]);
        }
    }
    float d = g_d1[b * H1 + i];
    #pragma unroll
    for (int j = 0; j < NC; j++)
        g_nu1f[(size_t)(b * NC + j) * H1 + i] = acc[j] * d;
}

// ---------------- K6: final-layer dots (warp per r) ------------------------
__global__ void k_fdots() {
    int gw   = (blockIdx.x * blockDim.x + threadIdx.x) >> 5;
    int lane = threadIdx.x & 31;
    if (gw >= NROWS) return;
    int b = gw / NC;
    const float* nur  = g_nu1f + (size_t)gw * H1;
    const float* nomr = g_nom1 + b * H1;
    const float* lmr  = g_l1m  + b * H1;
    float s1 = 0.f, s2 = 0.f;
    for (int i = lane; i < H1; i += 32) {
        float nu = nur[i];
        s1 += nu * nomr[i];
        s2 += fmaxf(-nu, 0.f) * lmr[i];
    }
    s1 = warp_sum(s1); s2 = warp_sum(s2);
    if (lane == 0) { g_afdot[gw] = s1; g_cross1f[gw] = s2; }
}

// ---------------- K7: output -----------------------------------------------
__global__ void k_out(float* __restrict__ out) {
    int r = threadIdx.x;
    if (r < NROWS)
        out[r] = -(g_afdot[r] + g_term[r] - g_Ef[r] + g_cross1f[r]);
}

// ---------------- launch ----------------------------------------------------
extern "C" void kernel_launch(void* const* d_in, const int* in_sizes, int n_in,
                              void* d_out, int out_size) {
    const float* x  = (const float*)d_in[0];
    const int*   y  = (const int*)  d_in[1];
    const float* W1 = (const float*)d_in[2];
    const float* b1 = (const float*)d_in[3];
    const float* W2 = (const float*)d_in[4];
    const float* b2 = (const float*)d_in[5];
    const float* W3 = (const float*)d_in[6];
    const float* b3 = (const float*)d_in[7];
    float* out = (float*)d_out;

    float* pE2; cudaGetSymbolAddress((void**)&pE2, g_E2);
    float* pEf; cudaGetSymbolAddress((void**)&pEf, g_Ef);
    float* pd1; cudaGetSymbolAddress((void**)&pd1, g_d1);
    float* pnu1f; cudaGetSymbolAddress((void**)&pnu1f, g_nu1f);

    k_r1<<<H1 / 8, 256>>>(W1);
    k_layer1<<<BATCH * H1 / 8, 256>>>(x, W1, b1);
    k_absgemm<<<dim3(H2 / 64, BATCH), 256>>>(W1, W2, pd1, pE2, 0);
    k_layer2<<<BATCH * H2 / 8, 256>>>(W2, b2);
    k_nu2<<<NROWS, 256>>>(W3, b2, b3, y);
    k_nu1f<<<dim3(H1 / 128, BATCH), 128>>>(W2);
    k_fdots<<<(NROWS + 7) / 8, 256>>>();
    k_absgemm<<<dim3(NROWS / 64, 1), 256>>>(W1, pnu1f, nullptr, pEf, 1);
    k_out<<<1, 512>>>(out);
}

// round 3
// speedup vs baseline: 4.2289x; 4.2289x over previous
#include <cuda_runtime.h>
#include <cuda_bf16.h>
#include <cstdint>

#define BATCH 32
#define IN_F  784
#define H1    1024
#define H2    1024
#define NC    10
#define EPSV  0.1f
#define NROWS (BATCH * NC)   // 320
#define MROWS1 384           // padded rows for final GEMM (3 x 128)

// ---------------- scratch (device globals; no allocation allowed) ----------
__device__ float g_r1[H1];
__device__ float g_nom1[BATCH * H1];
__device__ float g_d1[BATCH * H1];
__device__ float g_l1m[BATCH * H1];
__device__ float g_E2[BATCH * H2];
__device__ float g_d2[BATCH * H2];
__device__ float g_l2m[BATCH * H2];
__device__ float g_nu2[NROWS * H2];
__device__ float g_term[NROWS];
__device__ float g_nu1f[NROWS * H1];
__device__ __nv_bfloat16 g_nu1fb[MROWS1 * H1];    // rows 320..383 zero
__device__ __nv_bfloat16 g_W1T[H1 * H1];          // W1^T bf16, n-major; rows >=784 zero
__device__ __nv_bfloat16 g_Ab[(size_t)BATCH * H2 * H1];  // W2 * d1[b], bf16 (64MB)
__device__ float g_Ef[NROWS];
__device__ float g_afdot[NROWS];
__device__ float g_cross1f[NROWS];

// ---------------- helpers ---------------------------------------------------
__device__ __forceinline__ uint32_t smem_u32(const void* p) {
    uint32_t a;
    asm("{ .reg .u64 t; cvta.to.shared.u64 t, %1; cvt.u32.u64 %0, t; }" : "=r"(a) : "l"(p));
    return a;
}
__device__ __forceinline__ void cp_async16(uint32_t saddr, const void* gaddr) {
    asm volatile("cp.async.cg.shared.global [%0], [%1], 16;" :: "r"(saddr), "l"(gaddr));
}
__device__ __forceinline__ void cp_commit() {
    asm volatile("cp.async.commit_group;" ::: "memory");
}
template <int N>
__device__ __forceinline__ void cp_wait() {
    asm volatile("cp.async.wait_group %0;" :: "n"(N) : "memory");
}
__device__ __forceinline__ void ldsm_x4(uint32_t& r0, uint32_t& r1, uint32_t& r2,
                                        uint32_t& r3, uint32_t addr) {
    asm volatile("ldmatrix.sync.aligned.m8n8.x4.shared.b16 {%0,%1,%2,%3}, [%4];"
                 : "=r"(r0), "=r"(r1), "=r"(r2), "=r"(r3) : "r"(addr));
}
__device__ __forceinline__ void mma16816(float* c, const uint32_t* a, uint32_t b0,
                                         uint32_t b1) {
    asm volatile(
        "mma.sync.aligned.m16n8k16.row.col.f32.bf16.bf16.f32 "
        "{%0,%1,%2,%3}, {%4,%5,%6,%7}, {%8,%9}, {%0,%1,%2,%3};"
        : "+f"(c[0]), "+f"(c[1]), "+f"(c[2]), "+f"(c[3])
        : "r"(a[0]), "r"(a[1]), "r"(a[2]), "r"(a[3]), "r"(b0), "r"(b1));
}
__device__ __forceinline__ float warp_sum(float v) {
    #pragma unroll
    for (int o = 16; o > 0; o >>= 1) v += __shfl_xor_sync(0xFFFFFFFFu, v, o);
    return v;
}
__device__ __forceinline__ void relu_coeffs(float zl, float zu, float& d, float& lm) {
    if (zl >= 0.f)      { d = 1.f; lm = 0.f; }
    else if (zu <= 0.f) { d = 0.f; lm = 0.f; }
    else                { d = zu / (zu - zl); lm = zl; }
}

// ---------------- K0: r1 -----------------------------------------------------
__global__ void k_r1(const float* __restrict__ W1) {
    int gw = (blockIdx.x * blockDim.x + threadIdx.x) >> 5, lane = threadIdx.x & 31;
    if (gw >= H1) return;
    const float* row = W1 + gw * IN_F;
    float s = 0.f;
    for (int k = lane; k < IN_F; k += 32) s += fabsf(row[k]);
    s = warp_sum(s);
    if (lane == 0) g_r1[gw] = EPSV * s;
}

// ---------------- W1 transpose -> bf16 --------------------------------------
__global__ void k_w1t(const float* __restrict__ W1) {
    __shared__ float tile[32][33];
    int n0 = blockIdx.x * 32, i0 = blockIdx.y * 32;
    int tx = threadIdx.x, ty = threadIdx.y;      // 32 x 8
    #pragma unroll
    for (int r = 0; r < 4; r++) {
        int i = i0 + ty + 8 * r, n = n0 + tx;
        tile[ty + 8 * r][tx] = (n < IN_F) ? W1[i * IN_F + n] : 0.f;
    }
    __syncthreads();
    #pragma unroll
    for (int r = 0; r < 4; r++) {
        int n = n0 + ty + 8 * r;
        if (n < IN_F)
            g_W1T[(size_t)n * H1 + i0 + tx] = __float2bfloat16(tile[tx][ty + 8 * r]);
    }
}

// ---------------- zero pads --------------------------------------------------
__global__ void k_zero() {
    int idx = blockIdx.x * 256 + threadIdx.x;       // 480*256 = 122880
    uint32_t* w = (uint32_t*)g_W1T;
    w[IN_F * (H1 / 2) + idx] = 0u;                  // W1T rows 784..1023
    if (idx < 64 * (H1 / 2)) {
        uint32_t* nb = (uint32_t*)g_nu1fb;
        nb[NROWS * (H1 / 2) + idx] = 0u;            // nu1fb rows 320..383
    }
}

// ---------------- K1: layer-1 bounds ----------------------------------------
__global__ void k_layer1(const float* __restrict__ x, const float* __restrict__ W1,
                         const float* __restrict__ b1) {
    int gw = (blockIdx.x * blockDim.x + threadIdx.x) >> 5, lane = threadIdx.x & 31;
    int b = gw >> 10, j = gw & (H1 - 1);
    const float* xr = x + b * IN_F;
    const float* wr = W1 + j * IN_F;
    float s = 0.f;
    for (int k = lane; k < IN_F; k += 32) s += xr[k] * wr[k];
    s = warp_sum(s);
    if (lane == 0) {
        float nom = s + b1[j], r = g_r1[j], d, lm;
        relu_coeffs(nom - r, nom + r, d, lm);
        g_nom1[gw] = nom; g_d1[gw] = d; g_l1m[gw] = lm;
    }
}

// ---------------- A precompute: g_Ab = bf16(W2 * d1[b]) ---------------------
__global__ void k_scaleA(const float* __restrict__ W2) {
    size_t idx = ((size_t)blockIdx.x * 256 + threadIdx.x) * 8;    // 32M elems
    int b = (int)(idx >> 20);
    int i = (int)(idx & 1023);
    size_t wo = idx & 0xFFFFFu;
    float4 w0 = *(const float4*)(W2 + wo);
    float4 w1 = *(const float4*)(W2 + wo + 4);
    const float* dp = g_d1 + b * H1 + i;
    float4 e0 = *(const float4*)dp;
    float4 e1 = *(const float4*)(dp + 4);
    __nv_bfloat162 p0 = __floats2bfloat162_rn(w0.x * e0.x, w0.y * e0.y);
    __nv_bfloat162 p1 = __floats2bfloat162_rn(w0.z * e0.z, w0.w * e0.w);
    __nv_bfloat162 p2 = __floats2bfloat162_rn(w1.x * e1.x, w1.y * e1.y);
    __nv_bfloat162 p3 = __floats2bfloat162_rn(w1.z * e1.z, w1.w * e1.w);
    uint4 o;
    o.x = *(uint32_t*)&p0; o.y = *(uint32_t*)&p1;
    o.z = *(uint32_t*)&p2; o.w = *(uint32_t*)&p3;
    *(uint4*)(g_Ab + idx) = o;
}

// ---------------- tensor-core abs-row-sum GEMM (mma.sync bf16) --------------
// Eout[b*H2 + mtile*128 + r] = eps * sum_n | sum_i A[r,i] * W1T[n,i] |
// A rows: Abase + (b*rowstride + mtile*128) * H1
#define SASTRIDE 40   // halves per smem row (80B; conflict-free ldmatrix)
__global__ void __launch_bounds__(256) k_absgemm_mma(const __nv_bfloat16* __restrict__ Abase,
                                                     float* __restrict__ Eout,
                                                     int rowlimit) {
    __shared__ __align__(16) __nv_bfloat16 sA[2][128 * SASTRIDE];
    __shared__ __align__(16) __nv_bfloat16 sB[2][128 * SASTRIDE];
    __shared__ float sred[128][4];

    const int tid = threadIdx.x, lane = tid & 31, wid = tid >> 5;
    const int warp_m = wid & 1, warp_n = wid >> 1;
    const int mtile = blockIdx.x, b = blockIdx.z;
    const __nv_bfloat16* A = Abase + ((size_t)b * H2 + mtile * 128) * H1;
    const __nv_bfloat16* B = g_W1T;

    const int lrow = tid >> 1, lq = (tid & 1) * 2;     // loader: row, uint4 slot base

    // ldmatrix source coordinates
    const int aRow  = warp_m * 64 + (lane & 7) + ((lane >> 3) & 1) * 8;
    const int aColH = (lane >> 4) * 8;
    const int bRow  = warp_n * 32 + (lane & 7) + (lane >> 4) * 8;
    const int bColH = ((lane >> 3) & 1) * 8;

    const uint32_t sA0 = smem_u32(&sA[0][0]);
    const uint32_t sB0 = smem_u32(&sB[0][0]);
    const uint32_t BUFB = 128 * SASTRIDE * 2;   // bytes per buffer

    float rs[4][2];
    #pragma unroll
    for (int mi = 0; mi < 4; mi++) { rs[mi][0] = 0.f; rs[mi][1] = 0.f; }

    for (int nt = 0; nt < 8; nt++) {
        float acc[4][4][4];
        #pragma unroll
        for (int mi = 0; mi < 4; mi++)
            #pragma unroll
            for (int ni = 0; ni < 4; ni++)
                #pragma unroll
                for (int e = 0; e < 4; e++) acc[mi][ni][e] = 0.f;

        // prologue copy kt=0 -> buf0
        {
            #pragma unroll
            for (int s = 0; s < 2; s++) {
                int q = lq + s;
                cp_async16(sA0 + (lrow * SASTRIDE + q * 8) * 2,
                           A + (size_t)lrow * H1 + q * 8);
                cp_async16(sB0 + (lrow * SASTRIDE + q * 8) * 2,
                           B + (size_t)(nt * 128 + lrow) * H1 + q * 8);
            }
            cp_commit();
        }

        for (int kt = 0; kt < 32; kt++) {
            int buf = kt & 1;
            if (kt < 31) {
                int k0 = (kt + 1) * 32, nb = (kt + 1) & 1;
                #pragma unroll
                for (int s = 0; s < 2; s++) {
                    int q = lq + s;
                    cp_async16(sA0 + nb * BUFB + (lrow * SASTRIDE + q * 8) * 2,
                               A + (size_t)lrow * H1 + k0 + q * 8);
                    cp_async16(sB0 + nb * BUFB + (lrow * SASTRIDE + q * 8) * 2,
                               B + (size_t)(nt * 128 + lrow) * H1 + k0 + q * 8);
                }
                cp_commit();
                cp_wait<1>();
            } else {
                cp_wait<0>();
            }
            __syncthreads();

            uint32_t aBase = sA0 + buf * BUFB;
            uint32_t bBase = sB0 + buf * BUFB;
            #pragma unroll
            for (int ks = 0; ks < 2; ks++) {
                uint32_t af[4][4];
                #pragma unroll
                for (int mi = 0; mi < 4; mi++)
                    ldsm_x4(af[mi][0], af[mi][1], af[mi][2], af[mi][3],
                            aBase + ((aRow + mi * 16) * SASTRIDE + ks * 16 + aColH) * 2);
                uint32_t bf[2][4];
                #pragma unroll
                for (int np = 0; np < 2; np++)
                    ldsm_x4(bf[np][0], bf[np][1], bf[np][2], bf[np][3],
                            bBase + ((bRow + np * 16) * SASTRIDE + ks * 16 + bColH) * 2);
                #pragma unroll
                for (int mi = 0; mi < 4; mi++)
                    #pragma unroll
                    for (int ni = 0; ni < 4; ni++)
                        mma16816(acc[mi][ni], af[mi],
                                 bf[ni >> 1][(ni & 1) * 2], bf[ni >> 1][(ni & 1) * 2 + 1]);
            }
            __syncthreads();
        }

        #pragma unroll
        for (int mi = 0; mi < 4; mi++)
            #pragma unroll
            for (int ni = 0; ni < 4; ni++) {
                rs[mi][0] += fabsf(acc[mi][ni][0]) + fabsf(acc[mi][ni][1]);
                rs[mi][1] += fabsf(acc[mi][ni][2]) + fabsf(acc[mi][ni][3]);
            }
    }

    // reduce across the quad (lane&3), then across the 4 N-warps via smem
    #pragma unroll
    for (int mi = 0; mi < 4; mi++)
        #pragma unroll
        for (int h = 0; h < 2; h++) {
            float v = rs[mi][h];
            v += __shfl_xor_sync(0xFFFFFFFFu, v, 1);
            v += __shfl_xor_sync(0xFFFFFFFFu, v, 2);
            if ((lane & 3) == 0)
                sred[warp_m * 64 + mi * 16 + (lane >> 2) + h * 8][warp_n] = v;
        }
    __syncthreads();
    if (tid < 128) {
        float s = sred[tid][0] + sred[tid][1] + sred[tid][2] + sred[tid][3];
        int grow = mtile * 128 + tid;
        if (grow < rowlimit) Eout[b * H2 + grow] = EPSV * s;
    }
}

// ---------------- K3: layer-2 bounds ----------------------------------------
__global__ void k_layer2(const float* __restrict__ W2, const float* __restrict__ b2) {
    int gw = (blockIdx.x * blockDim.x + threadIdx.x) >> 5, lane = threadIdx.x & 31;
    int b = gw >> 10, j = gw & (H2 - 1);
    const float* w2r = W2 + (size_t)j * H1;
    const float* d1r = g_d1 + b * H1;
    const float* nomr = g_nom1 + b * H1;
    const float* lmr = g_l1m + b * H1;
    float s1 = 0.f, s2 = 0.f, s3 = 0.f;
    for (int i = lane; i < H1; i += 32) {
        float nu = w2r[i] * d1r[i];
        s1 += nu * nomr[i];
        float lm = lmr[i];
        s2 += fmaxf(-nu, 0.f) * lm;
        s3 += fmaxf(nu, 0.f) * lm;
    }
    s1 = warp_sum(s1); s2 = warp_sum(s2); s3 = warp_sum(s3);
    if (lane == 0) {
        float A = s1 + b2[j];
        float E = g_E2[gw];
        float d, lm;
        relu_coeffs(A - E + s2, A + E - s3, d, lm);
        g_d2[gw] = d; g_l2m[gw] = lm;
    }
}

// ---------------- K4: nu2 + bias/cross --------------------------------------
__global__ void k_nu2(const float* __restrict__ W3, const float* __restrict__ b2,
                      const float* __restrict__ b3, const int* __restrict__ y) {
    __shared__ float sAq[256], sBq[256];
    int r = blockIdx.x, b = r / NC, j = r % NC;
    int yb = y[b];
    const float* wy = W3 + (size_t)yb * H2;
    const float* wj = W3 + (size_t)j * H2;
    const float* d2r = g_d2 + b * H2;
    const float* lmr = g_l2m + b * H2;
    float sa = 0.f, sbv = 0.f;
    for (int t = threadIdx.x; t < H2; t += 256) {
        float nu = (wy[t] - wj[t]) * d2r[t];
        g_nu2[(size_t)r * H2 + t] = nu;
        sa += fmaxf(-nu, 0.f) * lmr[t];
        sbv += nu * b2[t];
    }
    sAq[threadIdx.x] = sa; sBq[threadIdx.x] = sbv;
    __syncthreads();
    for (int o = 128; o > 0; o >>= 1) {
        if (threadIdx.x < o) {
            sAq[threadIdx.x] += sAq[threadIdx.x + o];
            sBq[threadIdx.x] += sBq[threadIdx.x + o];
        }
        __syncthreads();
    }
    if (threadIdx.x == 0) g_term[r] = (b3[yb] - b3[j]) + sBq[0] + sAq[0];
}

// ---------------- K5: nu1f (fp32 + bf16 copy) -------------------------------
__global__ void k_nu1f(const float* __restrict__ W2) {
    __shared__ float snu[NC][64];
    int b = blockIdx.y;
    int i = blockIdx.x * 128 + threadIdx.x;
    float acc[NC];
    #pragma unroll
    for (int j = 0; j < NC; j++) acc[j] = 0.f;
    for (int t0 = 0; t0 < H2; t0 += 64) {
        __syncthreads();
        for (int idx = threadIdx.x; idx < NC * 64; idx += 128)
            snu[idx >> 6][idx & 63] =
                g_nu2[(size_t)(b * NC + (idx >> 6)) * H2 + t0 + (idx & 63)];
        __syncthreads();
        for (int t = 0; t < 64; t++) {
            float w = W2[(size_t)(t0 + t) * H1 + i];
            #pragma unroll
            for (int j = 0; j < NC; j++) acc[j] = fmaf(snu[j][t], w, acc[j]);
        }
    }
    float d = g_d1[b * H1 + i];
    #pragma unroll
    for (int j = 0; j < NC; j++) {
        float v = acc[j] * d;
        size_t o = (size_t)(b * NC + j) * H1 + i;
        g_nu1f[o] = v;
        g_nu1fb[o] = __float2bfloat16(v);
    }
}

// ---------------- K6: final-layer dots --------------------------------------
__global__ void k_fdots() {
    int gw = (blockIdx.x * blockDim.x + threadIdx.x) >> 5, lane = threadIdx.x & 31;
    if (gw >= NROWS) return;
    int b = gw / NC;
    const float* nur = g_nu1f + (size_t)gw * H1;
    const float* nomr = g_nom1 + b * H1;
    const float* lmr = g_l1m + b * H1;
    float s1 = 0.f, s2 = 0.f;
    for (int i = lane; i < H1; i += 32) {
        float nu = nur[i];
        s1 += nu * nomr[i];
        s2 += fmaxf(-nu, 0.f) * lmr[i];
    }
    s1 = warp_sum(s1); s2 = warp_sum(s2);
    if (lane == 0) { g_afdot[gw] = s1; g_cross1f[gw] = s2; }
}

// ---------------- K7: output -------------------------------------------------
__global__ void k_out(float* __restrict__ out) {
    int r = threadIdx.x;
    if (r < NROWS)
        out[r] = -(g_afdot[r] + g_term[r] - g_Ef[r] + g_cross1f[r]);
}

// ---------------- launch ------------------------------------------------------
extern "C" void kernel_launch(void* const* d_in, const int* in_sizes, int n_in,
                              void* d_out, int out_size) {
    const float* x  = (const float*)d_in[0];
    const int*   y  = (const int*)  d_in[1];
    const float* W1 = (const float*)d_in[2];
    const float* b1 = (const float*)d_in[3];
    const float* W2 = (const float*)d_in[4];
    const float* b2 = (const float*)d_in[5];
    const float* W3 = (const float*)d_in[6];
    const float* b3 = (const float*)d_in[7];
    float* out = (float*)d_out;

    float* pE2; cudaGetSymbolAddress((void**)&pE2, g_E2);
    float* pEf; cudaGetSymbolAddress((void**)&pEf, g_Ef);
    __nv_bfloat16* pAb;    cudaGetSymbolAddress((void**)&pAb, g_Ab);
    __nv_bfloat16* pnu1fb; cudaGetSymbolAddress((void**)&pnu1fb, g_nu1fb);

    k_r1<<<H1 / 8, 256>>>(W1);
    k_w1t<<<dim3(25, 32), dim3(32, 8)>>>(W1);
    k_zero<<<480, 256>>>();
    k_layer1<<<BATCH * H1 / 8, 256>>>(x, W1, b1);
    k_scaleA<<<16384, 256>>>(W2);
    k_absgemm_mma<<<dim3(8, 1, BATCH), 256>>>(pAb, pE2, H2);
    k_layer2<<<BATCH * H2 / 8, 256>>>(W2, b2);
    k_nu2<<<NROWS, 256>>>(W3, b2, b3, y);
    k_nu1f<<<dim3(H1 / 128, BATCH), 128>>>(W2);
    k_fdots<<<(NROWS + 7) / 8, 256>>>();
    k_absgemm_mma<<<dim3(3, 1, 1), 256>>>(pnu1fb, pEf, NROWS);
    k_out<<<1, 512>>>(out);
}

// round 4
// speedup vs baseline: 5.2936x; 1.2518x over previous
#include <cuda_runtime.h>
#include <cuda_bf16.h>
#include <cstdint>

#define BATCH 32
#define IN_F  784
#define H1    1024
#define H2    1024
#define NC    10
#define EPSV  0.1f
#define NROWS (BATCH * NC)   // 320
#define MROWS1 384           // padded rows for final GEMM (3 x 128)
#define SASTRIDE 40          // halves per smem row (80B)
#define STAGEB (128 * SASTRIDE * 2)   // 10240 bytes per stage per matrix

// ---------------- scratch (device globals) ----------------------------------
__device__ float g_r1[H1];
__device__ float g_nom1[BATCH * H1];
__device__ float g_d1[BATCH * H1];
__device__ float g_l1m[BATCH * H1];
__device__ float g_E2[BATCH * H2];
__device__ float g_d2[BATCH * H2];
__device__ float g_l2m[BATCH * H2];
__device__ float g_nu2[NROWS * H2];
__device__ float g_term[NROWS];
__device__ float g_nu1f[NROWS * H1];
__device__ __nv_bfloat16 g_nu1fb[MROWS1 * H1];    // rows 320..383 zero
__device__ __nv_bfloat16 g_W1T[H1 * H1];          // W1^T bf16; rows >=784 zero
__device__ __nv_bfloat16 g_Ab[(size_t)BATCH * H2 * H1];  // W2 * d1[b] (64MB)
__device__ float g_Efp[8][NROWS];
__device__ float g_afdot[NROWS];
__device__ float g_cross1f[NROWS];

// ---------------- helpers ----------------------------------------------------
__device__ __forceinline__ uint32_t smem_u32(const void* p) {
    uint32_t a;
    asm("{ .reg .u64 t; cvta.to.shared.u64 t, %1; cvt.u32.u64 %0, t; }" : "=r"(a) : "l"(p));
    return a;
}
__device__ __forceinline__ void cp_async16(uint32_t saddr, const void* gaddr) {
    asm volatile("cp.async.cg.shared.global [%0], [%1], 16;" :: "r"(saddr), "l"(gaddr));
}
__device__ __forceinline__ void cp_commit() {
    asm volatile("cp.async.commit_group;" ::: "memory");
}
template <int N>
__device__ __forceinline__ void cp_wait() {
    asm volatile("cp.async.wait_group %0;" :: "n"(N) : "memory");
}
__device__ __forceinline__ void ldsm_x4(uint32_t& r0, uint32_t& r1, uint32_t& r2,
                                        uint32_t& r3, uint32_t addr) {
    asm volatile("ldmatrix.sync.aligned.m8n8.x4.shared.b16 {%0,%1,%2,%3}, [%4];"
                 : "=r"(r0), "=r"(r1), "=r"(r2), "=r"(r3) : "r"(addr));
}
__device__ __forceinline__ void mma16816(float* c, const uint32_t* a, uint32_t b0,
                                         uint32_t b1) {
    asm volatile(
        "mma.sync.aligned.m16n8k16.row.col.f32.bf16.bf16.f32 "
        "{%0,%1,%2,%3}, {%4,%5,%6,%7}, {%8,%9}, {%0,%1,%2,%3};"
        : "+f"(c[0]), "+f"(c[1]), "+f"(c[2]), "+f"(c[3])
        : "r"(a[0]), "r"(a[1]), "r"(a[2]), "r"(a[3]), "r"(b0), "r"(b1));
}
__device__ __forceinline__ float warp_sum(float v) {
    #pragma unroll
    for (int o = 16; o > 0; o >>= 1) v += __shfl_xor_sync(0xFFFFFFFFu, v, o);
    return v;
}
__device__ __forceinline__ void relu_coeffs(float zl, float zu, float& d, float& lm) {
    if (zl >= 0.f)      { d = 1.f; lm = 0.f; }
    else if (zu <= 0.f) { d = 0.f; lm = 0.f; }
    else                { d = zu / (zu - zl); lm = zl; }
}

// ---------------- K0: r1 ------------------------------------------------------
__global__ void k_r1(const float* __restrict__ W1) {
    int gw = (blockIdx.x * blockDim.x + threadIdx.x) >> 5, lane = threadIdx.x & 31;
    if (gw >= H1) return;
    const float* row = W1 + gw * IN_F;
    float s = 0.f;
    for (int k = lane; k < IN_F; k += 32) s += fabsf(row[k]);
    s = warp_sum(s);
    if (lane == 0) g_r1[gw] = EPSV * s;
}

// ---------------- W1 transpose -> bf16 ---------------------------------------
__global__ void k_w1t(const float* __restrict__ W1) {
    __shared__ float tile[32][33];
    int n0 = blockIdx.x * 32, i0 = blockIdx.y * 32;
    int tx = threadIdx.x, ty = threadIdx.y;      // 32 x 8
    #pragma unroll
    for (int r = 0; r < 4; r++) {
        int i = i0 + ty + 8 * r, n = n0 + tx;
        tile[ty + 8 * r][tx] = (n < IN_F) ? W1[i * IN_F + n] : 0.f;
    }
    __syncthreads();
    #pragma unroll
    for (int r = 0; r < 4; r++) {
        int n = n0 + ty + 8 * r;
        if (n < IN_F)
            g_W1T[(size_t)n * H1 + i0 + tx] = __float2bfloat16(tile[tx][ty + 8 * r]);
    }
}

// ---------------- zero pads ---------------------------------------------------
__global__ void k_zero() {
    int idx = blockIdx.x * 256 + threadIdx.x;       // 480*256 = 122880
    uint32_t* w = (uint32_t*)g_W1T;
    w[IN_F * (H1 / 2) + idx] = 0u;                  // W1T rows 784..1023
    if (idx < 64 * (H1 / 2)) {
        uint32_t* nb = (uint32_t*)g_nu1fb;
        nb[NROWS * (H1 / 2) + idx] = 0u;            // nu1fb rows 320..383
    }
}

// ---------------- K1: layer-1 bounds ------------------------------------------
__global__ void k_layer1(const float* __restrict__ x, const float* __restrict__ W1,
                         const float* __restrict__ b1) {
    int gw = (blockIdx.x * blockDim.x + threadIdx.x) >> 5, lane = threadIdx.x & 31;
    int b = gw >> 10, j = gw & (H1 - 1);
    const float* xr = x + b * IN_F;
    const float* wr = W1 + j * IN_F;
    float s = 0.f;
    for (int k = lane; k < IN_F; k += 32) s += xr[k] * wr[k];
    s = warp_sum(s);
    if (lane == 0) {
        float nom = s + b1[j], r = g_r1[j], d, lm;
        relu_coeffs(nom - r, nom + r, d, lm);
        g_nom1[gw] = nom; g_d1[gw] = d; g_l1m[gw] = lm;
    }
}

// ---------------- A precompute: g_Ab = bf16(W2 * d1[b]) -----------------------
__global__ void k_scaleA(const float* __restrict__ W2) {
    size_t idx = ((size_t)blockIdx.x * 256 + threadIdx.x) * 8;    // 32M elems
    int b = (int)(idx >> 20);
    int i = (int)(idx & 1023);
    size_t wo = idx & 0xFFFFFu;
    float4 w0 = *(const float4*)(W2 + wo);
    float4 w1 = *(const float4*)(W2 + wo + 4);
    const float* dp = g_d1 + b * H1 + i;
    float4 e0 = *(const float4*)dp;
    float4 e1 = *(const float4*)(dp + 4);
    __nv_bfloat162 p0 = __floats2bfloat162_rn(w0.x * e0.x, w0.y * e0.y);
    __nv_bfloat162 p1 = __floats2bfloat162_rn(w0.z * e0.z, w0.w * e0.w);
    __nv_bfloat162 p2 = __floats2bfloat162_rn(w1.x * e1.x, w1.y * e1.y);
    __nv_bfloat162 p3 = __floats2bfloat162_rn(w1.z * e1.z, w1.w * e1.w);
    uint4 o;
    o.x = *(uint32_t*)&p0; o.y = *(uint32_t*)&p1;
    o.z = *(uint32_t*)&p2; o.w = *(uint32_t*)&p3;
    *(uint4*)(g_Ab + idx) = o;
}

// ---------------- tensor-core abs-row-sum GEMM (flattened 4-stage pipe) ------
// Writes RAW rowsum (no EPSV): Eout[out_off + row] = sum_n |sum_i A[row,i]*W1T[n,i]|
// nt range = [blockIdx.y*ntPerCta, +ntPerCta); out_off = b*H2 + blockIdx.y*chunkStride
__global__ void __launch_bounds__(256) k_absgemm_mma(const __nv_bfloat16* __restrict__ Abase,
                                                     float* __restrict__ Eout,
                                                     int rowlimit, int ntPerCta,
                                                     int chunkStride) {
    extern __shared__ char dsm[];
    __nv_bfloat16* sAp = (__nv_bfloat16*)dsm;
    __nv_bfloat16* sBp = sAp + 4 * 128 * SASTRIDE;
    float* sred = (float*)(sBp + 4 * 128 * SASTRIDE);   // [128][4]

    const int tid = threadIdx.x, lane = tid & 31, wid = tid >> 5;
    const int warp_m = wid & 1, warp_n = wid >> 1;
    const int mtile = blockIdx.x, b = blockIdx.z;
    const int ntBase = blockIdx.y * ntPerCta;
    const __nv_bfloat16* A = Abase + ((size_t)b * H2 + mtile * 128) * H1;
    const __nv_bfloat16* B = g_W1T;

    const int lrow = tid >> 1, lq = (tid & 1) * 2;

    const int aRow  = warp_m * 64 + (lane & 7) + ((lane >> 3) & 1) * 8;
    const int aColH = (lane >> 4) * 8;
    const int bRow  = warp_n * 32 + (lane & 7) + (lane >> 4) * 8;
    const int bColH = ((lane >> 3) & 1) * 8;

    const uint32_t sA0 = smem_u32(sAp);
    const uint32_t sB0 = smem_u32(sBp);

    auto copy_stage = [&](int g, int buf) {
        int kt = g & 31, nt = ntBase + (g >> 5);
        int k0 = kt * 32;
        #pragma unroll
        for (int s = 0; s < 2; s++) {
            int q = lq + s;
            uint32_t so = (uint32_t)buf * STAGEB + (lrow * SASTRIDE + q * 8) * 2;
            cp_async16(sA0 + so, A + (size_t)lrow * H1 + k0 + q * 8);
            cp_async16(sB0 + so, B + (size_t)(nt * 128 + lrow) * H1 + k0 + q * 8);
        }
    };

    const int total = ntPerCta * 32;
    copy_stage(0, 0); cp_commit();
    copy_stage(1, 1); cp_commit();
    copy_stage(2, 2); cp_commit();

    float rs[4][2];
    #pragma unroll
    for (int mi = 0; mi < 4; mi++) { rs[mi][0] = 0.f; rs[mi][1] = 0.f; }
    float acc[4][4][4];
    #pragma unroll
    for (int mi = 0; mi < 4; mi++)
        #pragma unroll
        for (int ni = 0; ni < 4; ni++)
            #pragma unroll
            for (int e = 0; e < 4; e++) acc[mi][ni][e] = 0.f;

    for (int g = 0; g < total; g++) {
        cp_wait<2>();
        __syncthreads();
        if (g + 3 < total) copy_stage(g + 3, (g + 3) & 3);
        cp_commit();

        int buf = g & 3;
        uint32_t aBase = sA0 + buf * STAGEB;
        uint32_t bBase = sB0 + buf * STAGEB;
        #pragma unroll
        for (int ks = 0; ks < 2; ks++) {
            uint32_t af[4][4];
            #pragma unroll
            for (int mi = 0; mi < 4; mi++)
                ldsm_x4(af[mi][0], af[mi][1], af[mi][2], af[mi][3],
                        aBase + ((aRow + mi * 16) * SASTRIDE + ks * 16 + aColH) * 2);
            uint32_t bf[2][4];
            #pragma unroll
            for (int np = 0; np < 2; np++)
                ldsm_x4(bf[np][0], bf[np][1], bf[np][2], bf[np][3],
                        bBase + ((bRow + np * 16) * SASTRIDE + ks * 16 + bColH) * 2);
            #pragma unroll
            for (int mi = 0; mi < 4; mi++)
                #pragma unroll
                for (int ni = 0; ni < 4; ni++)
                    mma16816(acc[mi][ni], af[mi],
                             bf[ni >> 1][(ni & 1) * 2], bf[ni >> 1][(ni & 1) * 2 + 1]);
        }

        if ((g & 31) == 31) {
            #pragma unroll
            for (int mi = 0; mi < 4; mi++)
                #pragma unroll
                for (int ni = 0; ni < 4; ni++) {
                    rs[mi][0] += fabsf(acc[mi][ni][0]) + fabsf(acc[mi][ni][1]);
                    rs[mi][1] += fabsf(acc[mi][ni][2]) + fabsf(acc[mi][ni][3]);
                    acc[mi][ni][0] = 0.f; acc[mi][ni][1] = 0.f;
                    acc[mi][ni][2] = 0.f; acc[mi][ni][3] = 0.f;
                }
        }
    }

    #pragma unroll
    for (int mi = 0; mi < 4; mi++)
        #pragma unroll
        for (int h = 0; h < 2; h++) {
            float v = rs[mi][h];
            v += __shfl_xor_sync(0xFFFFFFFFu, v, 1);
            v += __shfl_xor_sync(0xFFFFFFFFu, v, 2);
            if ((lane & 3) == 0)
                sred[(warp_m * 64 + mi * 16 + (lane >> 2) + h * 8) * 4 + warp_n] = v;
        }
    __syncthreads();
    if (tid < 128) {
        float s = sred[tid * 4 + 0] + sred[tid * 4 + 1] + sred[tid * 4 + 2] + sred[tid * 4 + 3];
        int grow = mtile * 128 + tid;
        if (grow < rowlimit)
            Eout[(size_t)b * H2 + (size_t)blockIdx.y * chunkStride + grow] = s;
    }
}

// ---------------- K3: layer-2 bounds ------------------------------------------
__global__ void k_layer2(const float* __restrict__ W2, const float* __restrict__ b2) {
    int gw = (blockIdx.x * blockDim.x + threadIdx.x) >> 5, lane = threadIdx.x & 31;
    int b = gw >> 10, j = gw & (H2 - 1);
    const float* w2r = W2 + (size_t)j * H1;
    const float* d1r = g_d1 + b * H1;
    const float* nomr = g_nom1 + b * H1;
    const float* lmr = g_l1m + b * H1;
    float s1 = 0.f, s2 = 0.f, s3 = 0.f;
    for (int i = lane; i < H1; i += 32) {
        float nu = w2r[i] * d1r[i];
        s1 += nu * nomr[i];
        float lm = lmr[i];
        s2 += fmaxf(-nu, 0.f) * lm;
        s3 += fmaxf(nu, 0.f) * lm;
    }
    s1 = warp_sum(s1); s2 = warp_sum(s2); s3 = warp_sum(s3);
    if (lane == 0) {
        float A = s1 + b2[j];
        float E = EPSV * g_E2[gw];
        float d, lm;
        relu_coeffs(A - E + s2, A + E - s3, d, lm);
        g_d2[gw] = d; g_l2m[gw] = lm;
    }
}

// ---------------- K4: nu2 + bias/cross ----------------------------------------
__global__ void k_nu2(const float* __restrict__ W3, const float* __restrict__ b2,
                      const float* __restrict__ b3, const int* __restrict__ y) {
    __shared__ float sAq[256], sBq[256];
    int r = blockIdx.x, b = r / NC, j = r % NC;
    int yb = y[b];
    const float* wy = W3 + (size_t)yb * H2;
    const float* wj = W3 + (size_t)j * H2;
    const float* d2r = g_d2 + b * H2;
    const float* lmr = g_l2m + b * H2;
    float sa = 0.f, sbv = 0.f;
    for (int t = threadIdx.x; t < H2; t += 256) {
        float nu = (wy[t] - wj[t]) * d2r[t];
        g_nu2[(size_t)r * H2 + t] = nu;
        sa += fmaxf(-nu, 0.f) * lmr[t];
        sbv += nu * b2[t];
    }
    sAq[threadIdx.x] = sa; sBq[threadIdx.x] = sbv;
    __syncthreads();
    for (int o = 128; o > 0; o >>= 1) {
        if (threadIdx.x < o) {
            sAq[threadIdx.x] += sAq[threadIdx.x + o];
            sBq[threadIdx.x] += sBq[threadIdx.x + o];
        }
        __syncthreads();
    }
    if (threadIdx.x == 0) g_term[r] = (b3[yb] - b3[j]) + sBq[0] + sAq[0];
}

// ---------------- K5: nu1f (fp32 + bf16 copy) ---------------------------------
__global__ void k_nu1f(const float* __restrict__ W2) {
    __shared__ float snu[NC][64];
    int b = blockIdx.y;
    int i = blockIdx.x * 128 + threadIdx.x;
    float acc[NC];
    #pragma unroll
    for (int j = 0; j < NC; j++) acc[j] = 0.f;
    for (int t0 = 0; t0 < H2; t0 += 64) {
        __syncthreads();
        for (int idx = threadIdx.x; idx < NC * 64; idx += 128)
            snu[idx >> 6][idx & 63] =
                g_nu2[(size_t)(b * NC + (idx >> 6)) * H2 + t0 + (idx & 63)];
        __syncthreads();
        for (int t = 0; t < 64; t++) {
            float w = W2[(size_t)(t0 + t) * H1 + i];
            #pragma unroll
            for (int j = 0; j < NC; j++) acc[j] = fmaf(snu[j][t], w, acc[j]);
        }
    }
    float d = g_d1[b * H1 + i];
    #pragma unroll
    for (int j = 0; j < NC; j++) {
        float v = acc[j] * d;
        size_t o = (size_t)(b * NC + j) * H1 + i;
        g_nu1f[o] = v;
        g_nu1fb[o] = __float2bfloat16(v);
    }
}

// ---------------- K6: final-layer dots ----------------------------------------
__global__ void k_fdots() {
    int gw = (blockIdx.x * blockDim.x + threadIdx.x) >> 5, lane = threadIdx.x & 31;
    if (gw >= NROWS) return;
    int b = gw / NC;
    const float* nur = g_nu1f + (size_t)gw * H1;
    const float* nomr = g_nom1 + b * H1;
    const float* lmr = g_l1m + b * H1;
    float s1 = 0.f, s2 = 0.f;
    for (int i = lane; i < H1; i += 32) {
        float nu = nur[i];
        s1 += nu * nomr[i];
        s2 += fmaxf(-nu, 0.f) * lmr[i];
    }
    s1 = warp_sum(s1); s2 = warp_sum(s2);
    if (lane == 0) { g_afdot[gw] = s1; g_cross1f[gw] = s2; }
}

// ---------------- K7: output ---------------------------------------------------
__global__ void k_out(float* __restrict__ out) {
    int r = threadIdx.x;
    if (r < NROWS) {
        float Ef = 0.f;
        #pragma unroll
        for (int c = 0; c < 8; c++) Ef += g_Efp[c][r];
        out[r] = -(g_afdot[r] + g_term[r] - EPSV * Ef + g_cross1f[r]);
    }
}

// ---------------- launch --------------------------------------------------------
extern "C" void kernel_launch(void* const* d_in, const int* in_sizes, int n_in,
                              void* d_out, int out_size) {
    const float* x  = (const float*)d_in[0];
    const int*   y  = (const int*)  d_in[1];
    const float* W1 = (const float*)d_in[2];
    const float* b1 = (const float*)d_in[3];
    const float* W2 = (const float*)d_in[4];
    const float* b2 = (const float*)d_in[5];
    const float* W3 = (const float*)d_in[6];
    const float* b3 = (const float*)d_in[7];
    float* out = (float*)d_out;

    float* pE2;  cudaGetSymbolAddress((void**)&pE2, g_E2);
    float* pEfp; cudaGetSymbolAddress((void**)&pEfp, g_Efp);
    __nv_bfloat16* pAb;    cudaGetSymbolAddress((void**)&pAb, g_Ab);
    __nv_bfloat16* pnu1fb; cudaGetSymbolAddress((void**)&pnu1fb, g_nu1fb);

    const int SMEM = 4 * STAGEB * 2 + 128 * 4 * 4 + 256;   // 84224
    cudaFuncSetAttribute(k_absgemm_mma, cudaFuncAttributeMaxDynamicSharedMemorySize, SMEM);

    k_r1<<<H1 / 8, 256>>>(W1);
    k_w1t<<<dim3(25, 32), dim3(32, 8)>>>(W1);
    k_zero<<<480, 256>>>();
    k_layer1<<<BATCH * H1 / 8, 256>>>(x, W1, b1);
    k_scaleA<<<16384, 256>>>(W2);
    k_absgemm_mma<<<dim3(8, 1, BATCH), 256, SMEM>>>(pAb, pE2, H2, 8, 0);
    k_layer2<<<BATCH * H2 / 8, 256>>>(W2, b2);
    k_nu2<<<NROWS, 256>>>(W3, b2, b3, y);
    k_nu1f<<<dim3(H1 / 128, BATCH), 128>>>(W2);
    k_fdots<<<(NROWS + 7) / 8, 256>>>();
    k_absgemm_mma<<<dim3(3, 8, 1), 256, SMEM>>>(pnu1fb, pEfp, NROWS, 1, NROWS);
    k_out<<<1, 512>>>(out);
}